// round 11
// baseline (speedup 1.0000x reference)
#include <cuda_runtime.h>
#include <cuda_bf16.h>
#include <math.h>

// CoxPHLoss without sorting, single cooperative kernel at FULL occupancy
// (grid = 296 = 2 blocks/SM on 148 SMs; launch_bounds guarantees 2/SM so all
// blocks are co-resident and the spin barrier is deadlock-free):
//   S[t]  = sum_{j: time_j == t} exp(risk_j)         (4096 buckets)
//   L[t]  = log( sum_{t' >= t} S[t'] )               (suffix logsum)
//   nll   = sum_t d_t * L[t] - sum_{i: event_i} risk_i
//
// Phase 1: stream + per-block shared 32-bit histograms (the smem-atomic pipe
//          needs 64 warps/SM to saturate -> 2 blocks/SM is the fast config),
//          PLAIN-STORE flush to per-block partials.
// Phase 2: grid spin-barrier, all blocks cooperatively reduce the 296
//          partials (fixed order -> deterministic).
// Phase 3: block 0 waits on arrival counter, suffix scan + NLL, self-cleans
//          the counters for graph replays.

#define NBINS    4096
#define GRIDC    296            // 2 blocks/SM x 148 SMs, all co-resident
#define THREADS1 1024
#define BINS_PER_BLOCK 14       // 296*14 = 4144 >= 4096

// Scratch (device globals; counters self-cleaned every launch)
__device__ float        g_partS[GRIDC * NBINS];
__device__ int          g_partD[GRIDC * NBINS];
__device__ double       g_partER[GRIDC];
__device__ double       g_S[NBINS];
__device__ int          g_Dsum[NBINS];
__device__ unsigned int g_bar1;
__device__ unsigned int g_bar2;

union SmemU {
    struct {
        float S[NBINS];     // 16 KB
        int   D[NBINS];     // 16 KB
    } h;
    double pref[NBINS];     // 32 KB (final-phase alias)
};

__global__ __launch_bounds__(THREADS1, 2)
void cox_coop_kernel(const float* __restrict__ risk,
                     const int* __restrict__ time_,
                     const int* __restrict__ event_,
                     float* __restrict__ out,
                     int n)
{
    __shared__ SmemU u;
    __shared__ double s_red[32];
    __shared__ long long s_dred[32];
    __shared__ double warpSums[32];

    const int tid = threadIdx.x;
    const int bid = blockIdx.x;
    const int lane = tid & 31, wid = tid >> 5;

    #pragma unroll
    for (int i = tid; i < NBINS; i += THREADS1) {
        u.h.S[i] = 0.0f;
        u.h.D[i] = 0;
    }
    __syncthreads();

    // ---------------- Phase 1: streaming histogram ----------------
    double er = 0.0;   // sum of risk over events (this thread)

    const int nvec = n >> 2;
    const float4* r4 = reinterpret_cast<const float4*>(risk);
    const int4*   t4 = reinterpret_cast<const int4*>(time_);
    const int4*   e4 = reinterpret_cast<const int4*>(event_);

    const int gstride = GRIDC * THREADS1;
    const int gtid = bid * THREADS1 + tid;

    for (int i = gtid; i < nvec; i += gstride) {
        float4 r = r4[i];
        int4   t = t4[i];
        int4   e = e4[i];

        int t0 = t.x & (NBINS - 1);
        int t1 = t.y & (NBINS - 1);
        int t2 = t.z & (NBINS - 1);
        int t3 = t.w & (NBINS - 1);

        atomicAdd(&u.h.S[t0], __expf(r.x));
        atomicAdd(&u.h.S[t1], __expf(r.y));
        atomicAdd(&u.h.S[t2], __expf(r.z));
        atomicAdd(&u.h.S[t3], __expf(r.w));

        if (e.x) { atomicAdd(&u.h.D[t0], 1); er += (double)r.x; }
        if (e.y) { atomicAdd(&u.h.D[t1], 1); er += (double)r.y; }
        if (e.z) { atomicAdd(&u.h.D[t2], 1); er += (double)r.z; }
        if (e.w) { atomicAdd(&u.h.D[t3], 1); er += (double)r.w; }
    }

    // scalar tail (n not multiple of 4)
    for (int j = (nvec << 2) + gtid; j < n; j += gstride) {
        float r = risk[j];
        int   t = time_[j] & (NBINS - 1);
        atomicAdd(&u.h.S[t], __expf(r));
        if (event_[j]) { atomicAdd(&u.h.D[t], 1); er += (double)r; }
    }

    // block-reduce er -> g_partER[bid]
    #pragma unroll
    for (int off = 16; off > 0; off >>= 1)
        er += __shfl_down_sync(0xffffffffu, er, off);
    if (lane == 0) s_red[wid] = er;
    __syncthreads();
    if (wid == 0) {
        double v = s_red[lane];
        #pragma unroll
        for (int off = 16; off > 0; off >>= 1)
            v += __shfl_down_sync(0xffffffffu, v, off);
        if (lane == 0) g_partER[bid] = v;
    }
    __syncthreads();

    // plain-store flush of the shared histogram (coalesced)
    #pragma unroll
    for (int k = tid; k < NBINS; k += THREADS1) {
        g_partS[bid * NBINS + k] = u.h.S[k];
        g_partD[bid * NBINS + k] = u.h.D[k];
    }

    // ---------------- grid barrier #1 (release/acquire) ----------------
    __threadfence();
    __syncthreads();
    if (tid == 0) {
        atomicAdd(&g_bar1, 1u);
        while (atomicAdd(&g_bar1, 0u) < GRIDC)
            __nanosleep(64);
    }
    __syncthreads();

    // ---------------- Phase 2: cooperative combine ----------------
    // Warp w of block b owns bin b*14 + w (w < 14). Lanes split the 296
    // partials (lane<8 -> 10, else 9; fixed order -> deterministic).
    if (wid < BINS_PER_BLOCK) {
        int bin = bid * BINS_PER_BLOCK + wid;
        if (bin < NBINS) {
            int cnt   = (lane < 8) ? 10 : 9;
            int start = (lane < 8) ? lane * 10 : 80 + (lane - 8) * 9;
            double s = 0.0;
            int d = 0;
            for (int k = 0; k < cnt; k++) {
                int p = start + k;
                s += (double)g_partS[p * NBINS + bin];
                d += g_partD[p * NBINS + bin];
            }
            #pragma unroll
            for (int off = 16; off > 0; off >>= 1) {
                s += __shfl_down_sync(0xffffffffu, s, off);
                d += __shfl_down_sync(0xffffffffu, d, off);
            }
            if (lane == 0) {
                g_S[bin]    = s;
                g_Dsum[bin] = d;
            }
        }
    }

    // ---------------- grid barrier #2 (arrive; only block 0 waits) -----
    __threadfence();
    __syncthreads();
    if (tid == 0)
        atomicAdd(&g_bar2, 1u);
    if (bid != 0)
        return;
    if (tid == 0) {
        while (atomicAdd(&g_bar2, 0u) < GRIDC)
            __nanosleep(64);
    }
    __syncthreads();

    // ---------------- Phase 3: suffix scan + NLL (block 0) -------------
    const int base = tid * 4;   // 4 reversed-index elements per thread

    double v[4];
    int dloc[4];
    double run = 0.0;
    #pragma unroll
    for (int k = 0; k < 4; k++) {
        int t = NBINS - 1 - (base + k);
        run += g_S[t];
        v[k] = run;
        dloc[k] = g_Dsum[t];
    }
    double total = run;

    // warp inclusive scan of per-thread totals
    double x = total;
    #pragma unroll
    for (int off = 1; off < 32; off <<= 1) {
        double y = __shfl_up_sync(0xffffffffu, x, off);
        if (lane >= off) x += y;
    }
    double wexcl = x - total;
    if (lane == 31) warpSums[wid] = x;
    __syncthreads();

    if (wid == 0) {
        double ws = warpSums[lane];
        double xx = ws;
        #pragma unroll
        for (int off = 1; off < 32; off <<= 1) {
            double y = __shfl_up_sync(0xffffffffu, xx, off);
            if (lane >= off) xx += y;
        }
        warpSums[lane] = xx - ws;   // exclusive warp offsets
    }
    __syncthreads();   // also separates union reuse (hist -> pref)

    double off0 = warpSums[wid] + wexcl;
    #pragma unroll
    for (int k = 0; k < 4; k++)
        u.pref[base + k] = off0 + v[k];
    __syncthreads();

    // d_t * log(suffix_sum[t]); suffix_sum[t] = pref[4095 - t]
    double c = 0.0;
    long long dtot = 0;
    #pragma unroll
    for (int k = 0; k < 4; k++) {
        int j = base + k;
        int d = dloc[k];
        dtot += d;
        if (d > 0) c += (double)d * log(u.pref[j]);
    }
    // subtract event-risk sum (fixed order across tid => deterministic)
    if (tid < GRIDC) c -= g_partER[tid];

    #pragma unroll
    for (int off = 16; off > 0; off >>= 1) {
        c    += __shfl_down_sync(0xffffffffu, c, off);
        dtot += __shfl_down_sync(0xffffffffu, dtot, off);
    }
    if (lane == 0) { s_red[wid] = c; s_dred[wid] = dtot; }
    __syncthreads();
    if (wid == 0) {
        double cc = s_red[lane];
        long long dd = s_dred[lane];
        #pragma unroll
        for (int off = 16; off > 0; off >>= 1) {
            cc += __shfl_down_sync(0xffffffffu, cc, off);
            dd += __shfl_down_sync(0xffffffffu, dd, off);
        }
        if (lane == 0) {
            out[0] = (dd > 0) ? (float)cc : 0.0f;
            g_bar1 = 0u;           // self-clean for next graph replay
            g_bar2 = 0u;
        }
    }
}

// ---------------------------------------------------------------------------
extern "C" void kernel_launch(void* const* d_in, const int* in_sizes, int n_in,
                              void* d_out, int out_size)
{
    const float* risk  = (const float*)d_in[0];
    const int*   time_ = (const int*)d_in[1];
    const int*   event_= (const int*)d_in[2];
    float* out = (float*)d_out;
    int n = in_sizes[0];

    cox_coop_kernel<<<GRIDC, THREADS1>>>(risk, time_, event_, out, n);
}